// round 15
// baseline (speedup 1.0000x reference)
#include <cuda_runtime.h>
#include <cuda_fp16.h>
#include <cuda_bf16.h>
#include <cstdint>

#define N_NODES 50000
#define N_EDGES 800000
#define N_GRAPHS 1024
#define DIM 300
#define N_LAYERS 5
#define FEAT 256
#define EPS 1e-5f
#define NBLK_SCAN ((N_NODES + 255) / 256)   // 196

// padded plane geometry (no predicates in GEMM staging)
#define AROWS 50048        // 391 * 128
#define ACOLS 304          // 19 * 16
#define WROWS 304
#define WCOLS 320

// ---------------- scratch (static device globals; no allocation) -------------
__device__ __align__(16) __nv_bfloat16 g_ahi[AROWS * ACOLS];  // 30.4 MB
__device__ __align__(16) __nv_bfloat16 g_alo[AROWS * ACOLS];
__device__ __align__(16) __nv_bfloat16 g_whi[N_LAYERS * WROWS * WCOLS];
__device__ __align__(16) __nv_bfloat16 g_wlo[N_LAYERS * WROWS * WCOLS];
__device__ __half g_hwh[N_NODES * DIM];   // h @ W[l] in fp16 (30 MB)
__device__ float  g_agg[N_NODES * DIM];   // pre-BN accumulation
__device__ float  g_stats[N_LAYERS * 2 * DIM];
__device__ float  g_coef[2 * DIM];        // current layer BN scale/shift
__device__ float  g_emsum[N_LAYERS * N_NODES];  // per-node edge-emb sums
__device__ float  g_hg[N_GRAPHS * DIM];
__device__ float  g_hid[N_GRAPHS * FEAT];
// CSR build
__device__ int g_deg[N_NODES];
__device__ int g_incl[N_NODES];
__device__ int g_bsum[NBLK_SCAN];
__device__ int g_boff[NBLK_SCAN];
__device__ int g_cursor[N_NODES];
__device__ int g_start[N_NODES + 1];
__device__ int g_csr[N_EDGES];           // row | (attr<<16)
__device__ int g_gstart[N_GRAPHS + 1];

// ---------------- weight split: W -> bf16 hi/lo padded planes ----------------
__global__ void wconv_kernel(const float* __restrict__ W) {
    int i = blockIdx.x * blockDim.x + threadIdx.x;
    if (i >= N_LAYERS * WROWS * WCOLS) return;
    int l = i / (WROWS * WCOLS);
    int r = i - l * (WROWS * WCOLS);
    int k = r / WCOLS, n = r - k * WCOLS;
    float v = (k < DIM && n < DIM) ? W[(size_t)l * DIM * DIM + k * DIM + n] : 0.f;
    __nv_bfloat16 h = __float2bfloat16_rn(v);
    g_whi[i] = h;
    g_wlo[i] = __float2bfloat16_rn(v - __bfloat162float(h));
}

// ---------------- node embedding -> layer-0 A planes; zero deg/stats ---------
__global__ void embed_kernel(const int* __restrict__ x,
                             const float* __restrict__ emb1,
                             const float* __restrict__ emb2) {
    int i = blockIdx.x * blockDim.x + threadIdx.x;
    if (i < N_LAYERS * 2 * DIM) g_stats[i] = 0.f;
    if (i < N_NODES) g_deg[i] = 0;
    if (i >= AROWS * ACOLS) return;
    int n = i / ACOLS, d = i - n * ACOLS;
    float v = 0.f;
    if (n < N_NODES && d < DIM)
        v = emb1[x[2 * n] * DIM + d] + emb2[x[2 * n + 1] * DIM + d];
    __nv_bfloat16 h = __float2bfloat16_rn(v);
    g_ahi[i] = h;
    g_alo[i] = __float2bfloat16_rn(v - __bfloat162float(h));
}

// ---------------- per-layer BN+ReLU convert: g_agg -> A planes (float4) ------
// 300 = 75*4 exactly; pad rows/cols stay zero from embed (never rewritten).
__global__ void convert_kernel() {
    int i = blockIdx.x * blockDim.x + threadIdx.x;  // chunk id
    if (i >= N_NODES * 75) return;
    int n = i / 75, c = i - n * 75;
    int d = 4 * c;
    const float4 v = *(const float4*)&g_agg[n * DIM + d];
    const float4 s = *(const float4*)&g_coef[d];
    const float4 t = *(const float4*)&g_coef[DIM + d];
    float f0 = fmaxf(v.x * s.x + t.x, 0.f);
    float f1 = fmaxf(v.y * s.y + t.y, 0.f);
    float f2 = fmaxf(v.z * s.z + t.z, 0.f);
    float f3 = fmaxf(v.w * s.w + t.w, 0.f);
    __nv_bfloat16 h0 = __float2bfloat16_rn(f0);
    __nv_bfloat16 h1 = __float2bfloat16_rn(f1);
    __nv_bfloat16 h2 = __float2bfloat16_rn(f2);
    __nv_bfloat16 h3 = __float2bfloat16_rn(f3);
    unsigned hu0 = (unsigned)__bfloat16_as_ushort(h0) |
                   ((unsigned)__bfloat16_as_ushort(h1) << 16);
    unsigned hu1 = (unsigned)__bfloat16_as_ushort(h2) |
                   ((unsigned)__bfloat16_as_ushort(h3) << 16);
    __nv_bfloat16 l0 = __float2bfloat16_rn(f0 - __bfloat162float(h0));
    __nv_bfloat16 l1 = __float2bfloat16_rn(f1 - __bfloat162float(h1));
    __nv_bfloat16 l2 = __float2bfloat16_rn(f2 - __bfloat162float(h2));
    __nv_bfloat16 l3 = __float2bfloat16_rn(f3 - __bfloat162float(h3));
    unsigned lu0 = (unsigned)__bfloat16_as_ushort(l0) |
                   ((unsigned)__bfloat16_as_ushort(l1) << 16);
    unsigned lu1 = (unsigned)__bfloat16_as_ushort(l2) |
                   ((unsigned)__bfloat16_as_ushort(l3) << 16);
    size_t off = (size_t)n * ACOLS + d;
    *(uint2*)&g_ahi[off] = make_uint2(hu0, hu1);
    *(uint2*)&g_alo[off] = make_uint2(lu0, lu1);
}

// ---------------- CSR build ---------------------------------------------------
__global__ void hist_kernel(const int* __restrict__ ei) {
    int e = blockIdx.x * blockDim.x + threadIdx.x;
    if (e >= N_EDGES) return;
    atomicAdd(&g_deg[ei[N_EDGES + e]], 1);
}

__global__ void scan1_kernel() {
    __shared__ int s[256];
    int tid = threadIdx.x;
    int i = blockIdx.x * 256 + tid;
    int v = (i < N_NODES) ? g_deg[i] : 0;
    s[tid] = v;
    __syncthreads();
#pragma unroll
    for (int off = 1; off < 256; off <<= 1) {
        int t = (tid >= off) ? s[tid - off] : 0;
        __syncthreads();
        s[tid] += t;
        __syncthreads();
    }
    if (i < N_NODES) g_incl[i] = s[tid];
    if (tid == 255) g_bsum[blockIdx.x] = s[255];
}

__global__ void scan2_kernel() {
    __shared__ int s[256];
    int tid = threadIdx.x;
    s[tid] = (tid < NBLK_SCAN) ? g_bsum[tid] : 0;
    __syncthreads();
#pragma unroll
    for (int off = 1; off < 256; off <<= 1) {
        int t = (tid >= off) ? s[tid - off] : 0;
        __syncthreads();
        s[tid] += t;
        __syncthreads();
    }
    if (tid < NBLK_SCAN) g_boff[tid] = s[tid] - g_bsum[tid];
}

__global__ void scan3_kernel() {
    int i = blockIdx.x * blockDim.x + threadIdx.x;
    if (i >= N_NODES) return;
    g_start[i + 1] = g_incl[i] + g_boff[i >> 8];
    g_cursor[i] = 0;
    if (i == 0) g_start[0] = 0;
}

__global__ void fill_kernel(const int* __restrict__ ei,
                            const int* __restrict__ ea) {
    int e = blockIdx.x * blockDim.x + threadIdx.x;
    if (e >= N_EDGES) return;
    int row = ei[e];
    int col = ei[N_EDGES + e];
    int attr = ea[2 * e] * 3 + ea[2 * e + 1];  // 0..8
    int pos = g_start[col] + atomicAdd(&g_cursor[col], 1);
    g_csr[pos] = row | (attr << 16);
}

// per-node sum of scalar edge embeddings, all layers at once
__global__ void emsum_kernel(const float* __restrict__ e1,
                             const float* __restrict__ e2) {
    __shared__ float tab[N_LAYERS][9];
    int tid = threadIdx.x;
    if (tid < N_LAYERS * 9) {
        int l = tid / 9, a = tid % 9;
        tab[l][a] = e1[l * 5 + a / 3] + e2[l * 3 + a % 3];
    }
    __syncthreads();
    int n = blockIdx.x * blockDim.x + tid;
    if (n >= N_NODES) return;
    float s[N_LAYERS] = {0.f, 0.f, 0.f, 0.f, 0.f};
    int e0 = g_start[n], e1i = g_start[n + 1];
    for (int e = e0; e < e1i; e++) {
        int a = g_csr[e] >> 16;
#pragma unroll
        for (int l = 0; l < N_LAYERS; l++) s[l] += tab[l][a];
    }
#pragma unroll
    for (int l = 0; l < N_LAYERS; l++) g_emsum[l * N_NODES + n] = s[l];
}

// ---------------- 3xBF16 tensor-core GEMM (3-stage cp.async + ldmatrix) ------
#define MMA_BF16(cc, A0, A1, A2, A3, B0, B1)                                   \
    asm volatile(                                                              \
        "mma.sync.aligned.m16n8k16.row.col.f32.bf16.bf16.f32 "                 \
        "{%0,%1,%2,%3},{%4,%5,%6,%7},{%8,%9},{%0,%1,%2,%3};"                   \
        : "+f"(cc[0]), "+f"(cc[1]), "+f"(cc[2]), "+f"(cc[3])                   \
        : "r"(A0), "r"(A1), "r"(A2), "r"(A3), "r"(B0), "r"(B1));

__device__ __forceinline__ void ldsm_x4(unsigned& r0, unsigned& r1,
                                        unsigned& r2, unsigned& r3,
                                        unsigned addr) {
    asm volatile("ldmatrix.sync.aligned.m8n8.x4.shared.b16 {%0,%1,%2,%3}, [%4];"
                 : "=r"(r0), "=r"(r1), "=r"(r2), "=r"(r3) : "r"(addr));
}
__device__ __forceinline__ void ldsm_x4_t(unsigned& r0, unsigned& r1,
                                          unsigned& r2, unsigned& r3,
                                          unsigned addr) {
    asm volatile(
        "ldmatrix.sync.aligned.m8n8.x4.trans.shared.b16 {%0,%1,%2,%3}, [%4];"
        : "=r"(r0), "=r"(r1), "=r"(r2), "=r"(r3) : "r"(addr));
}
__device__ __forceinline__ void cp16(void* dst_smem, const void* src) {
    unsigned d = (unsigned)__cvta_generic_to_shared(dst_smem);
    asm volatile("cp.async.cg.shared.global [%0], [%1], 16;"
                 :: "r"(d), "l"(src) : "memory");
}

#define NKT 19   // ceil(300/16)
#define A_RS 24  // A row stride in bf16 (48 B -> group 3m mod 8, conflict-free)
#define B_RS 72  // B row stride in bf16 (144 B -> group k mod 8, conflict-free)
#define GSTAGES 3
#define A_PLANE (128 * A_RS)   // bf16 per stage per plane
#define B_PLANE (16 * B_RS)
#define GEMM_SMEM ((size_t)GSTAGES * (2 * A_PLANE + 2 * B_PLANE) * 2)  // 50688 B

__global__ __launch_bounds__(256)
void gemm_layer_tc(const __nv_bfloat16* __restrict__ Whi,
                   const __nv_bfloat16* __restrict__ Wlo) {
    extern __shared__ __align__(16) __nv_bfloat16 smp[];
    __nv_bfloat16* Ahi = smp;                          // [GSTAGES][128][A_RS]
    __nv_bfloat16* Alo = Ahi + GSTAGES * A_PLANE;
    __nv_bfloat16* Bhi = Alo + GSTAGES * A_PLANE;      // [GSTAGES][16][B_RS]
    __nv_bfloat16* Blo = Bhi + GSTAGES * B_PLANE;

    const int tid = threadIdx.x;
    const int lane = tid & 31;
    const int warp = tid >> 5;
    const int g = lane >> 2;      // 0..7
    const int tg = lane & 3;      // 0..3
    const int wm = warp >> 1;     // 0..3 (m)
    const int wn = warp & 1;      // 0..1 (n)
    const int m0 = blockIdx.y * 128;
    const int n0 = blockIdx.x * 64;

    float c[2][4][4];
#pragma unroll
    for (int im = 0; im < 2; im++)
#pragma unroll
        for (int in = 0; in < 4; in++)
#pragma unroll
            for (int j = 0; j < 4; j++) c[im][in][j] = 0.f;

    // A staging: row a_m = tid&127, k-half (8 bf16 = 16 B) = tid>>7
    const int a_m = tid & 127;
    const int a_kh = tid >> 7;
    const size_t a_goff = (size_t)(m0 + a_m) * ACOLS + a_kh * 8;
    // B staging: 128 chunks of 16 B per plane; tid<128 -> hi plane, else lo
    const int b_idx = tid & 127;
    const int b_k = b_idx >> 3;            // 0..15
    const int b_nc = (b_idx & 7) * 8;      // 0..56
    const bool b_is_hi = (tid < 128);
    const __nv_bfloat16* wsrc = b_is_hi ? Whi : Wlo;

    auto stage = [&](int kt) {
        int buf = kt % GSTAGES;
        cp16(Ahi + (buf * 128 + a_m) * A_RS + a_kh * 8,
             g_ahi + a_goff + kt * 16);
        cp16(Alo + (buf * 128 + a_m) * A_RS + a_kh * 8,
             g_alo + a_goff + kt * 16);
        __nv_bfloat16* bd = (b_is_hi ? Bhi : Blo) + (buf * 16 + b_k) * B_RS + b_nc;
        cp16(bd, wsrc + (size_t)(kt * 16 + b_k) * WCOLS + n0 + b_nc);
        asm volatile("cp.async.commit_group;" ::: "memory");
    };

    // ldmatrix per-thread source offsets
    const int a_row = (lane & 15);
    const int a_chk = (lane >> 4) * 8;
    const int b_row = ((lane >> 3) & 1) * 8 + (lane & 7);
    const int b_chk = (lane >> 4) * 8;

    stage(0);
    stage(1);

#pragma unroll 1
    for (int kt = 0; kt < NKT; kt++) {
        const int buf = kt % GSTAGES;
        if (kt < NKT - 1)
            asm volatile("cp.async.wait_group 1;" ::: "memory");
        else
            asm volatile("cp.async.wait_group 0;" ::: "memory");
        __syncthreads();

        {
            unsigned ah[2][4], al[2][4];
#pragma unroll
            for (int im = 0; im < 2; im++) {
                int mrow = buf * 128 + wm * 32 + im * 16 + a_row;
                unsigned ahh = (unsigned)__cvta_generic_to_shared(
                    Ahi + mrow * A_RS + a_chk);
                unsigned all_ = (unsigned)__cvta_generic_to_shared(
                    Alo + mrow * A_RS + a_chk);
                ldsm_x4(ah[im][0], ah[im][1], ah[im][2], ah[im][3], ahh);
                ldsm_x4(al[im][0], al[im][1], al[im][2], al[im][3], all_);
            }
            unsigned bh[4][2], bl[4][2];
#pragma unroll
            for (int pair = 0; pair < 2; pair++) {
                int ncol = wn * 32 + pair * 16 + b_chk;
                int brw = buf * 16 + b_row;
                unsigned bhh = (unsigned)__cvta_generic_to_shared(
                    Bhi + brw * B_RS + ncol);
                unsigned bll = (unsigned)__cvta_generic_to_shared(
                    Blo + brw * B_RS + ncol);
                ldsm_x4_t(bh[2 * pair][0], bh[2 * pair][1],
                          bh[2 * pair + 1][0], bh[2 * pair + 1][1], bhh);
                ldsm_x4_t(bl[2 * pair][0], bl[2 * pair][1],
                          bl[2 * pair + 1][0], bl[2 * pair + 1][1], bll);
            }
#pragma unroll
            for (int im = 0; im < 2; im++)
#pragma unroll
                for (int in = 0; in < 4; in++) {
                    MMA_BF16(c[im][in], al[im][0], al[im][1], al[im][2],
                             al[im][3], bh[in][0], bh[in][1]);
                    MMA_BF16(c[im][in], ah[im][0], ah[im][1], ah[im][2],
                             ah[im][3], bl[in][0], bl[in][1]);
                    MMA_BF16(c[im][in], ah[im][0], ah[im][1], ah[im][2],
                             ah[im][3], bh[in][0], bh[in][1]);
                }
        }

        // Stage kt+2 into buffer (kt+2)%3 = (kt-1)%3. All threads finished
        // reading that buffer (compute kt-1) before this iteration's barrier.
        if (kt + 2 < NKT) stage(kt + 2);
    }

    // ---- epilogue: write g_hwh (fp16, half2 stores) ----
#pragma unroll
    for (int in = 0; in < 4; in++) {
        int ncol = n0 + wn * 32 + in * 8 + 2 * tg;
        if (ncol >= DIM) continue;
#pragma unroll
        for (int im = 0; im < 2; im++) {
            int r0 = m0 + wm * 32 + im * 16 + g;
            if (r0 < N_NODES)
                *(__half2*)&g_hwh[r0 * DIM + ncol] =
                    __floats2half2_rn(c[im][in][0], c[im][in][1]);
            int r1 = r0 + 8;
            if (r1 < N_NODES)
                *(__half2*)&g_hwh[r1 * DIM + ncol] =
                    __floats2half2_rn(c[im][in][2], c[im][in][3]);
        }
    }
}

// ------- CSR aggregation: 4 nodes/block, segmented sub-loops, fused stats ----
#define AGG_NODES 4
#define AGG_BUF 640

__global__ __launch_bounds__(160)
void agg_kernel(const float* __restrict__ bl,
                const float* __restrict__ e1,
                const float* __restrict__ e2,
                int l) {
    __shared__ int s_pk[AGG_BUF];
    const int n0 = blockIdx.x * AGG_NODES;
    const int tid = threadIdx.x;
    const int b0 = g_start[n0];
    const int b1 = g_start[n0 + 1];
    const int b2 = g_start[n0 + 2];
    const int b3 = g_start[n0 + 3];
    const int b4 = g_start[n0 + 4];
    const float selfE = e1[l * 5 + 4] + e2[l * 3 + 0];

    float ax0 = 0.f, ay0 = 0.f, ax1 = 0.f, ay1 = 0.f;
    float ax2 = 0.f, ay2 = 0.f, ax3 = 0.f, ay3 = 0.f;

    for (int base = b0; base < b4; base += AGG_BUF) {
        int cnt = min(AGG_BUF, b4 - base);
        for (int i = tid; i < cnt; i += 160) s_pk[i] = g_csr[base + i];
        __syncthreads();
        if (tid < 150) {
            const int hi = base + cnt;
            // Per-node sub-ranges inside this batch: no per-edge owner logic.
#define AGG_SEG(LOB, HIB, AX, AY)                                              \
            {                                                                  \
                int lo = max((LOB), base) - base;                              \
                int up = min((HIB), hi) - base;                                \
                _Pragma("unroll 4")                                            \
                for (int i = lo; i < up; i++) {                                \
                    int row = s_pk[i] & 0xFFFF;                                \
                    float2 f = __half22float2(                                 \
                        *(const __half2*)&g_hwh[row * DIM + 2 * tid]);         \
                    AX += f.x; AY += f.y;                                      \
                }                                                              \
            }
            AGG_SEG(b0, b1, ax0, ay0)
            AGG_SEG(b1, b2, ax1, ay1)
            AGG_SEG(b2, b3, ax2, ay2)
            AGG_SEG(b3, b4, ax3, ay3)
#undef AGG_SEG
        }
        __syncthreads();
    }

    if (tid < 150) {
        const float blv0 = bl[2 * tid], blv1 = bl[2 * tid + 1];
        float ssx = 0.f, ssy = 0.f, qqx = 0.f, qqy = 0.f;  // BN partials
#define AGG_WR(J, AX, AY)                                                      \
        {                                                                      \
            int n = n0 + (J);                                                  \
            float em = g_emsum[l * N_NODES + n] + selfE;                       \
            float2 s = __half22float2(                                         \
                *(const __half2*)&g_hwh[n * DIM + 2 * tid]);                   \
            float2 o;                                                          \
            o.x = (AX) + s.x + blv0 + em;                                      \
            o.y = (AY) + s.y + blv1 + em;                                      \
            *(float2*)&g_agg[n * DIM + 2 * tid] = o;                           \
            ssx += o.x; ssy += o.y;                                            \
            qqx += o.x * o.x; qqy += o.y * o.y;                                \
        }
        AGG_WR(0, ax0, ay0)
        AGG_WR(1, ax1, ay1)
        AGG_WR(2, ax2, ay2)
        AGG_WR(3, ax3, ay3)
#undef AGG_WR
        // fused BN statistics (replaces stats_kernel)
        float* st = &g_stats[l * 2 * DIM];
        atomicAdd(&st[2 * tid], ssx);
        atomicAdd(&st[2 * tid + 1], ssy);
        atomicAdd(&st[DIM + 2 * tid], qqx);
        atomicAdd(&st[DIM + 2 * tid + 1], qqy);
    }
}

// ---------------- batch norm coefficients ------------------------------------
__global__ void coef_kernel(const float* __restrict__ gamma,
                            const float* __restrict__ beta, int l) {
    int d = blockIdx.x * blockDim.x + threadIdx.x;
    if (d >= DIM) return;
    const float* st = &g_stats[l * 2 * DIM];
    const float inv_n = 1.0f / (float)N_NODES;
    float mu = st[d] * inv_n;
    float var = st[DIM + d] * inv_n - mu * mu;
    float s = rsqrtf(var + EPS) * gamma[l * DIM + d];
    g_coef[d] = s;
    g_coef[DIM + d] = beta[l * DIM + d] - mu * s;
}

// ---------------- pool (applies final BN; batch sorted -> segments) ----------
__global__ void gbound_kernel(const int* __restrict__ batch) {
    int g = blockIdx.x * blockDim.x + threadIdx.x;
    if (g > N_GRAPHS) return;
    int lo = 0, hi = N_NODES;
    while (lo < hi) {
        int mid = (lo + hi) >> 1;
        if (batch[mid] < g) lo = mid + 1; else hi = mid;
    }
    g_gstart[g] = lo;
}

__global__ __launch_bounds__(128)
void pool_kernel() {
    const int g = blockIdx.x;
    const int tid = threadIdx.x;
    const int gs = g_gstart[g], ge = g_gstart[g + 1];
    const int d0 = tid, d1 = tid + 128, d2 = tid + 256;
    float a0 = 0.f, a1 = 0.f, a2 = 0.f;
#pragma unroll 2
    for (int r = gs; r < ge; r++) {
        const float* p = g_agg + r * DIM;
        a0 += p[d0];
        a1 += p[d1];
        if (d2 < DIM) a2 += p[d2];
    }
    float inv = 1.0f / fmaxf((float)(ge - gs), 1.0f);
    float* op = g_hg + g * DIM;
    op[d0] = (a0 * inv) * g_coef[d0] + g_coef[DIM + d0];
    op[d1] = (a1 * inv) * g_coef[d1] + g_coef[DIM + d1];
    if (d2 < DIM) op[d2] = (a2 * inv) * g_coef[d2] + g_coef[DIM + d2];
}

// ---------------- head MLPs --------------------------------------------------
__global__ void gemm_feat(const float* __restrict__ fw,
                          const float* __restrict__ fb,
                          float* __restrict__ hfeat) {
    __shared__ float sh[DIM];
    int g = blockIdx.x;
    int t = threadIdx.x;  // 256
    for (int k = t; k < DIM; k += FEAT) sh[k] = g_hg[g * DIM + k];
    __syncthreads();
    float acc = fb[t];
    for (int k = 0; k < DIM; k++) acc += sh[k] * fw[k * FEAT + t];
    hfeat[g * FEAT + t] = acc;
}

__global__ void gemm_mlp1(const float* __restrict__ hfeat,
                          const float* __restrict__ w1,
                          const float* __restrict__ b1) {
    __shared__ float sh[FEAT];
    int g = blockIdx.x;
    int t = threadIdx.x;  // 256
    sh[t] = hfeat[g * FEAT + t];
    __syncthreads();
    float acc = b1[t];
    for (int k = 0; k < FEAT; k++) acc += sh[k] * w1[k * FEAT + t];
    g_hid[g * FEAT + t] = fmaxf(acc, 0.f);
}

__global__ void gemm_mlp2(const float* __restrict__ w2,
                          const float* __restrict__ b2,
                          float* __restrict__ out) {
    __shared__ float sh[FEAT];
    int g = blockIdx.x;
    int t = threadIdx.x;  // 128
    sh[t] = g_hid[g * FEAT + t];
    sh[t + 128] = g_hid[g * FEAT + t + 128];
    __syncthreads();
    float acc = b2[t];
    for (int k = 0; k < FEAT; k++) acc += sh[k] * w2[k * 128 + t];
    out[g * 128 + t] = acc;
}

// ---------------- launch -----------------------------------------------------
extern "C" void kernel_launch(void* const* d_in, const int* in_sizes, int n_in,
                              void* d_out, int out_size) {
    const int*   x     = (const int*)d_in[0];
    const int*   ei    = (const int*)d_in[1];
    const int*   ea    = (const int*)d_in[2];
    const int*   batch = (const int*)d_in[3];
    const float* emb1  = (const float*)d_in[4];
    const float* emb2  = (const float*)d_in[5];
    const float* W     = (const float*)d_in[6];
    const float* b     = (const float*)d_in[7];
    const float* e1    = (const float*)d_in[8];
    const float* e2    = (const float*)d_in[9];
    const float* gamma = (const float*)d_in[10];
    const float* beta  = (const float*)d_in[11];
    const float* fw    = (const float*)d_in[12];
    const float* fb    = (const float*)d_in[13];
    const float* w1    = (const float*)d_in[14];
    const float* b1    = (const float*)d_in[15];
    const float* w2    = (const float*)d_in[16];
    const float* b2    = (const float*)d_in[17];

    float* hfeat_out = (float*)d_out;
    float* final_out = (float*)d_out + N_GRAPHS * FEAT;

    __nv_bfloat16 *d_whi, *d_wlo;
    cudaGetSymbolAddress((void**)&d_whi, g_whi);
    cudaGetSymbolAddress((void**)&d_wlo, g_wlo);

    cudaFuncSetAttribute(gemm_layer_tc,
                         cudaFuncAttributeMaxDynamicSharedMemorySize,
                         (int)GEMM_SMEM);

    dim3 ggrid((DIM + 63) / 64, (N_NODES + 127) / 128);  // 5 x 391
    const int plane_blocks = (AROWS * ACOLS + 255) / 256;
    const int conv_blocks = (N_NODES * 75 + 255) / 256;

    // Launch order keeps gemm_layer_tc(l=0) at position #4 for ncu attribution.
    wconv_kernel<<<(N_LAYERS * WROWS * WCOLS + 255) / 256, 256>>>(W);   // 1
    embed_kernel<<<plane_blocks, 256>>>(x, emb1, emb2);                 // 2
    hist_kernel<<<(N_EDGES + 255) / 256, 256>>>(ei);                    // 3
    gemm_layer_tc<<<ggrid, 256, GEMM_SMEM>>>(d_whi, d_wlo);             // 4 (l=0)
    scan1_kernel<<<NBLK_SCAN, 256>>>();                                 // 5
    scan2_kernel<<<1, 256>>>();                                         // 6
    scan3_kernel<<<(N_NODES + 255) / 256, 256>>>();                     // 7
    fill_kernel<<<(N_EDGES + 255) / 256, 256>>>(ei, ea);                // 8
    emsum_kernel<<<NBLK_SCAN, 256>>>(e1, e2);                           // 9

    for (int l = 0; l < N_LAYERS; l++) {
        if (l > 0)
            gemm_layer_tc<<<ggrid, 256, GEMM_SMEM>>>(
                d_whi + (size_t)l * WROWS * WCOLS,
                d_wlo + (size_t)l * WROWS * WCOLS);
        agg_kernel<<<N_NODES / AGG_NODES, 160>>>(b + l * DIM, e1, e2, l);
        coef_kernel<<<2, 256>>>(gamma, beta, l);
        if (l < N_LAYERS - 1)
            convert_kernel<<<conv_blocks, 256>>>();
    }

    gbound_kernel<<<(N_GRAPHS + 256) / 256, 256>>>(batch);
    pool_kernel<<<N_GRAPHS, 128>>>();

    gemm_feat<<<N_GRAPHS, FEAT>>>(fw, fb, hfeat_out);
    gemm_mlp1<<<N_GRAPHS, FEAT>>>(hfeat_out, w1, b1);
    gemm_mlp2<<<N_GRAPHS, 128>>>(w2, b2, final_out);
}

// round 16
// speedup vs baseline: 1.2944x; 1.2944x over previous
#include <cuda_runtime.h>
#include <cuda_fp16.h>
#include <cuda_bf16.h>
#include <cstdint>

#define N_NODES 50000
#define N_EDGES 800000
#define N_GRAPHS 1024
#define DIM 300
#define N_LAYERS 5
#define FEAT 256
#define EPS 1e-5f
#define NBLK_SCAN ((N_NODES + 255) / 256)   // 196
#define NSC 32   // stat copies (contention spreading)

// padded plane geometry (no predicates in GEMM staging)
#define AROWS 50048        // 391 * 128
#define ACOLS 304          // 19 * 16
#define WROWS 304
#define WCOLS 320

// ---------------- scratch (static device globals; no allocation) -------------
__device__ __align__(16) __nv_bfloat16 g_ahi[AROWS * ACOLS];  // 30.4 MB
__device__ __align__(16) __nv_bfloat16 g_alo[AROWS * ACOLS];
__device__ __align__(16) __nv_bfloat16 g_whi[N_LAYERS * WROWS * WCOLS];
__device__ __align__(16) __nv_bfloat16 g_wlo[N_LAYERS * WROWS * WCOLS];
__device__ __half g_hwh[N_NODES * DIM];   // h @ W[l] in fp16 (30 MB)
__device__ float  g_agg[N_NODES * DIM];   // pre-BN accumulation
__device__ float  g_stats[N_LAYERS * NSC * 2 * DIM];  // 32 copies per layer
__device__ float  g_coef[2 * DIM];        // current layer BN scale/shift
__device__ float  g_emsum[N_LAYERS * N_NODES];  // per-node edge-emb sums
__device__ float  g_hg[N_GRAPHS * DIM];
__device__ float  g_hid[N_GRAPHS * FEAT];
// CSR build
__device__ int g_deg[N_NODES];
__device__ int g_incl[N_NODES];
__device__ int g_bsum[NBLK_SCAN];
__device__ int g_boff[NBLK_SCAN];
__device__ int g_cursor[N_NODES];
__device__ int g_start[N_NODES + 1];
__device__ int g_csr[N_EDGES];           // row | (attr<<16)
__device__ int g_gstart[N_GRAPHS + 1];

// ---------------- weight split: W -> bf16 hi/lo padded planes ----------------
__global__ void wconv_kernel(const float* __restrict__ W) {
    int i = blockIdx.x * blockDim.x + threadIdx.x;
    if (i >= N_LAYERS * WROWS * WCOLS) return;
    int l = i / (WROWS * WCOLS);
    int r = i - l * (WROWS * WCOLS);
    int k = r / WCOLS, n = r - k * WCOLS;
    float v = (k < DIM && n < DIM) ? W[(size_t)l * DIM * DIM + k * DIM + n] : 0.f;
    __nv_bfloat16 h = __float2bfloat16_rn(v);
    g_whi[i] = h;
    g_wlo[i] = __float2bfloat16_rn(v - __bfloat162float(h));
}

// ---------------- node embedding -> layer-0 A planes; zero deg/stats ---------
__global__ void embed_kernel(const int* __restrict__ x,
                             const float* __restrict__ emb1,
                             const float* __restrict__ emb2) {
    int i = blockIdx.x * blockDim.x + threadIdx.x;
    if (i < N_LAYERS * NSC * 2 * DIM) g_stats[i] = 0.f;
    if (i < N_NODES) g_deg[i] = 0;
    if (i >= AROWS * ACOLS) return;
    int n = i / ACOLS, d = i - n * ACOLS;
    float v = 0.f;
    if (n < N_NODES && d < DIM)
        v = emb1[x[2 * n] * DIM + d] + emb2[x[2 * n + 1] * DIM + d];
    __nv_bfloat16 h = __float2bfloat16_rn(v);
    g_ahi[i] = h;
    g_alo[i] = __float2bfloat16_rn(v - __bfloat162float(h));
}

// ---------------- per-layer BN+ReLU convert: g_agg -> A planes (float4) ------
// 300 = 75*4 exactly; pad rows/cols stay zero from embed (never rewritten).
__global__ void convert_kernel() {
    int i = blockIdx.x * blockDim.x + threadIdx.x;  // chunk id
    if (i >= N_NODES * 75) return;
    int n = i / 75, c = i - n * 75;
    int d = 4 * c;
    const float4 v = *(const float4*)&g_agg[n * DIM + d];
    const float4 s = *(const float4*)&g_coef[d];
    const float4 t = *(const float4*)&g_coef[DIM + d];
    float f0 = fmaxf(v.x * s.x + t.x, 0.f);
    float f1 = fmaxf(v.y * s.y + t.y, 0.f);
    float f2 = fmaxf(v.z * s.z + t.z, 0.f);
    float f3 = fmaxf(v.w * s.w + t.w, 0.f);
    __nv_bfloat16 h0 = __float2bfloat16_rn(f0);
    __nv_bfloat16 h1 = __float2bfloat16_rn(f1);
    __nv_bfloat16 h2 = __float2bfloat16_rn(f2);
    __nv_bfloat16 h3 = __float2bfloat16_rn(f3);
    unsigned hu0 = (unsigned)__bfloat16_as_ushort(h0) |
                   ((unsigned)__bfloat16_as_ushort(h1) << 16);
    unsigned hu1 = (unsigned)__bfloat16_as_ushort(h2) |
                   ((unsigned)__bfloat16_as_ushort(h3) << 16);
    __nv_bfloat16 l0 = __float2bfloat16_rn(f0 - __bfloat162float(h0));
    __nv_bfloat16 l1 = __float2bfloat16_rn(f1 - __bfloat162float(h1));
    __nv_bfloat16 l2 = __float2bfloat16_rn(f2 - __bfloat162float(h2));
    __nv_bfloat16 l3 = __float2bfloat16_rn(f3 - __bfloat162float(h3));
    unsigned lu0 = (unsigned)__bfloat16_as_ushort(l0) |
                   ((unsigned)__bfloat16_as_ushort(l1) << 16);
    unsigned lu1 = (unsigned)__bfloat16_as_ushort(l2) |
                   ((unsigned)__bfloat16_as_ushort(l3) << 16);
    size_t off = (size_t)n * ACOLS + d;
    *(uint2*)&g_ahi[off] = make_uint2(hu0, hu1);
    *(uint2*)&g_alo[off] = make_uint2(lu0, lu1);
}

// ---------------- CSR build ---------------------------------------------------
__global__ void hist_kernel(const int* __restrict__ ei) {
    int e = blockIdx.x * blockDim.x + threadIdx.x;
    if (e >= N_EDGES) return;
    atomicAdd(&g_deg[ei[N_EDGES + e]], 1);
}

__global__ void scan1_kernel() {
    __shared__ int s[256];
    int tid = threadIdx.x;
    int i = blockIdx.x * 256 + tid;
    int v = (i < N_NODES) ? g_deg[i] : 0;
    s[tid] = v;
    __syncthreads();
#pragma unroll
    for (int off = 1; off < 256; off <<= 1) {
        int t = (tid >= off) ? s[tid - off] : 0;
        __syncthreads();
        s[tid] += t;
        __syncthreads();
    }
    if (i < N_NODES) g_incl[i] = s[tid];
    if (tid == 255) g_bsum[blockIdx.x] = s[255];
}

__global__ void scan2_kernel() {
    __shared__ int s[256];
    int tid = threadIdx.x;
    s[tid] = (tid < NBLK_SCAN) ? g_bsum[tid] : 0;
    __syncthreads();
#pragma unroll
    for (int off = 1; off < 256; off <<= 1) {
        int t = (tid >= off) ? s[tid - off] : 0;
        __syncthreads();
        s[tid] += t;
        __syncthreads();
    }
    if (tid < NBLK_SCAN) g_boff[tid] = s[tid] - g_bsum[tid];
}

__global__ void scan3_kernel() {
    int i = blockIdx.x * blockDim.x + threadIdx.x;
    if (i >= N_NODES) return;
    g_start[i + 1] = g_incl[i] + g_boff[i >> 8];
    g_cursor[i] = 0;
    if (i == 0) g_start[0] = 0;
}

__global__ void fill_kernel(const int* __restrict__ ei,
                            const int* __restrict__ ea) {
    int e = blockIdx.x * blockDim.x + threadIdx.x;
    if (e >= N_EDGES) return;
    int row = ei[e];
    int col = ei[N_EDGES + e];
    int attr = ea[2 * e] * 3 + ea[2 * e + 1];  // 0..8
    int pos = g_start[col] + atomicAdd(&g_cursor[col], 1);
    g_csr[pos] = row | (attr << 16);
}

// per-node sum of scalar edge embeddings, all layers at once
__global__ void emsum_kernel(const float* __restrict__ e1,
                             const float* __restrict__ e2) {
    __shared__ float tab[N_LAYERS][9];
    int tid = threadIdx.x;
    if (tid < N_LAYERS * 9) {
        int l = tid / 9, a = tid % 9;
        tab[l][a] = e1[l * 5 + a / 3] + e2[l * 3 + a % 3];
    }
    __syncthreads();
    int n = blockIdx.x * blockDim.x + tid;
    if (n >= N_NODES) return;
    float s[N_LAYERS] = {0.f, 0.f, 0.f, 0.f, 0.f};
    int e0 = g_start[n], e1i = g_start[n + 1];
    for (int e = e0; e < e1i; e++) {
        int a = g_csr[e] >> 16;
#pragma unroll
        for (int l = 0; l < N_LAYERS; l++) s[l] += tab[l][a];
    }
#pragma unroll
    for (int l = 0; l < N_LAYERS; l++) g_emsum[l * N_NODES + n] = s[l];
}

// ---------------- 3xBF16 tensor-core GEMM (3-stage cp.async + ldmatrix) ------
#define MMA_BF16(cc, A0, A1, A2, A3, B0, B1)                                   \
    asm volatile(                                                              \
        "mma.sync.aligned.m16n8k16.row.col.f32.bf16.bf16.f32 "                 \
        "{%0,%1,%2,%3},{%4,%5,%6,%7},{%8,%9},{%0,%1,%2,%3};"                   \
        : "+f"(cc[0]), "+f"(cc[1]), "+f"(cc[2]), "+f"(cc[3])                   \
        : "r"(A0), "r"(A1), "r"(A2), "r"(A3), "r"(B0), "r"(B1));

__device__ __forceinline__ void ldsm_x4(unsigned& r0, unsigned& r1,
                                        unsigned& r2, unsigned& r3,
                                        unsigned addr) {
    asm volatile("ldmatrix.sync.aligned.m8n8.x4.shared.b16 {%0,%1,%2,%3}, [%4];"
                 : "=r"(r0), "=r"(r1), "=r"(r2), "=r"(r3) : "r"(addr));
}
__device__ __forceinline__ void ldsm_x4_t(unsigned& r0, unsigned& r1,
                                          unsigned& r2, unsigned& r3,
                                          unsigned addr) {
    asm volatile(
        "ldmatrix.sync.aligned.m8n8.x4.trans.shared.b16 {%0,%1,%2,%3}, [%4];"
        : "=r"(r0), "=r"(r1), "=r"(r2), "=r"(r3) : "r"(addr));
}
__device__ __forceinline__ void cp16(void* dst_smem, const void* src) {
    unsigned d = (unsigned)__cvta_generic_to_shared(dst_smem);
    asm volatile("cp.async.cg.shared.global [%0], [%1], 16;"
                 :: "r"(d), "l"(src) : "memory");
}

#define NKT 19   // ceil(300/16)
#define A_RS 24  // A row stride in bf16 (48 B -> group 3m mod 8, conflict-free)
#define B_RS 72  // B row stride in bf16 (144 B -> group k mod 8, conflict-free)
#define GSTAGES 3
#define A_PLANE (128 * A_RS)   // bf16 per stage per plane
#define B_PLANE (16 * B_RS)
#define GEMM_SMEM ((size_t)GSTAGES * (2 * A_PLANE + 2 * B_PLANE) * 2)  // 50688 B

__global__ __launch_bounds__(256)
void gemm_layer_tc(const __nv_bfloat16* __restrict__ Whi,
                   const __nv_bfloat16* __restrict__ Wlo) {
    extern __shared__ __align__(16) __nv_bfloat16 smp[];
    __nv_bfloat16* Ahi = smp;                          // [GSTAGES][128][A_RS]
    __nv_bfloat16* Alo = Ahi + GSTAGES * A_PLANE;
    __nv_bfloat16* Bhi = Alo + GSTAGES * A_PLANE;      // [GSTAGES][16][B_RS]
    __nv_bfloat16* Blo = Bhi + GSTAGES * B_PLANE;

    const int tid = threadIdx.x;
    const int lane = tid & 31;
    const int warp = tid >> 5;
    const int g = lane >> 2;      // 0..7
    const int tg = lane & 3;      // 0..3
    const int wm = warp >> 1;     // 0..3 (m)
    const int wn = warp & 1;      // 0..1 (n)
    const int m0 = blockIdx.y * 128;
    const int n0 = blockIdx.x * 64;

    float c[2][4][4];
#pragma unroll
    for (int im = 0; im < 2; im++)
#pragma unroll
        for (int in = 0; in < 4; in++)
#pragma unroll
            for (int j = 0; j < 4; j++) c[im][in][j] = 0.f;

    // A staging: row a_m = tid&127, k-half (8 bf16 = 16 B) = tid>>7
    const int a_m = tid & 127;
    const int a_kh = tid >> 7;
    const size_t a_goff = (size_t)(m0 + a_m) * ACOLS + a_kh * 8;
    // B staging: 128 chunks of 16 B per plane; tid<128 -> hi plane, else lo
    const int b_idx = tid & 127;
    const int b_k = b_idx >> 3;            // 0..15
    const int b_nc = (b_idx & 7) * 8;      // 0..56
    const bool b_is_hi = (tid < 128);
    const __nv_bfloat16* wsrc = b_is_hi ? Whi : Wlo;

    auto stage = [&](int kt) {
        int buf = kt % GSTAGES;
        cp16(Ahi + (buf * 128 + a_m) * A_RS + a_kh * 8,
             g_ahi + a_goff + kt * 16);
        cp16(Alo + (buf * 128 + a_m) * A_RS + a_kh * 8,
             g_alo + a_goff + kt * 16);
        __nv_bfloat16* bd = (b_is_hi ? Bhi : Blo) + (buf * 16 + b_k) * B_RS + b_nc;
        cp16(bd, wsrc + (size_t)(kt * 16 + b_k) * WCOLS + n0 + b_nc);
        asm volatile("cp.async.commit_group;" ::: "memory");
    };

    // ldmatrix per-thread source offsets
    const int a_row = (lane & 15);
    const int a_chk = (lane >> 4) * 8;
    const int b_row = ((lane >> 3) & 1) * 8 + (lane & 7);
    const int b_chk = (lane >> 4) * 8;

    stage(0);
    stage(1);

#pragma unroll 1
    for (int kt = 0; kt < NKT; kt++) {
        const int buf = kt % GSTAGES;
        if (kt < NKT - 1)
            asm volatile("cp.async.wait_group 1;" ::: "memory");
        else
            asm volatile("cp.async.wait_group 0;" ::: "memory");
        __syncthreads();

        {
            unsigned ah[2][4], al[2][4];
#pragma unroll
            for (int im = 0; im < 2; im++) {
                int mrow = buf * 128 + wm * 32 + im * 16 + a_row;
                unsigned ahh = (unsigned)__cvta_generic_to_shared(
                    Ahi + mrow * A_RS + a_chk);
                unsigned all_ = (unsigned)__cvta_generic_to_shared(
                    Alo + mrow * A_RS + a_chk);
                ldsm_x4(ah[im][0], ah[im][1], ah[im][2], ah[im][3], ahh);
                ldsm_x4(al[im][0], al[im][1], al[im][2], al[im][3], all_);
            }
            unsigned bh[4][2], bl[4][2];
#pragma unroll
            for (int pair = 0; pair < 2; pair++) {
                int ncol = wn * 32 + pair * 16 + b_chk;
                int brw = buf * 16 + b_row;
                unsigned bhh = (unsigned)__cvta_generic_to_shared(
                    Bhi + brw * B_RS + ncol);
                unsigned bll = (unsigned)__cvta_generic_to_shared(
                    Blo + brw * B_RS + ncol);
                ldsm_x4_t(bh[2 * pair][0], bh[2 * pair][1],
                          bh[2 * pair + 1][0], bh[2 * pair + 1][1], bhh);
                ldsm_x4_t(bl[2 * pair][0], bl[2 * pair][1],
                          bl[2 * pair + 1][0], bl[2 * pair + 1][1], bll);
            }
#pragma unroll
            for (int im = 0; im < 2; im++)
#pragma unroll
                for (int in = 0; in < 4; in++) {
                    MMA_BF16(c[im][in], al[im][0], al[im][1], al[im][2],
                             al[im][3], bh[in][0], bh[in][1]);
                    MMA_BF16(c[im][in], ah[im][0], ah[im][1], ah[im][2],
                             ah[im][3], bl[in][0], bl[in][1]);
                    MMA_BF16(c[im][in], ah[im][0], ah[im][1], ah[im][2],
                             ah[im][3], bh[in][0], bh[in][1]);
                }
        }

        // Stage kt+2 into buffer (kt+2)%3 = (kt-1)%3. All threads finished
        // reading that buffer (compute kt-1) before this iteration's barrier.
        if (kt + 2 < NKT) stage(kt + 2);
    }

    // ---- epilogue: write g_hwh (fp16, half2 stores) ----
#pragma unroll
    for (int in = 0; in < 4; in++) {
        int ncol = n0 + wn * 32 + in * 8 + 2 * tg;
        if (ncol >= DIM) continue;
#pragma unroll
        for (int im = 0; im < 2; im++) {
            int r0 = m0 + wm * 32 + im * 16 + g;
            if (r0 < N_NODES)
                *(__half2*)&g_hwh[r0 * DIM + ncol] =
                    __floats2half2_rn(c[im][in][0], c[im][in][1]);
            int r1 = r0 + 8;
            if (r1 < N_NODES)
                *(__half2*)&g_hwh[r1 * DIM + ncol] =
                    __floats2half2_rn(c[im][in][2], c[im][in][3]);
        }
    }
}

// -- CSR aggregation: 4 nodes/block, segmented sub-loops, 32-copy fused stats --
#define AGG_NODES 4
#define AGG_BUF 640

__global__ __launch_bounds__(160)
void agg_kernel(const float* __restrict__ bl,
                const float* __restrict__ e1,
                const float* __restrict__ e2,
                int l) {
    __shared__ int s_pk[AGG_BUF];
    const int n0 = blockIdx.x * AGG_NODES;
    const int tid = threadIdx.x;
    const int b0 = g_start[n0];
    const int b1 = g_start[n0 + 1];
    const int b2 = g_start[n0 + 2];
    const int b3 = g_start[n0 + 3];
    const int b4 = g_start[n0 + 4];
    const float selfE = e1[l * 5 + 4] + e2[l * 3 + 0];

    float ax0 = 0.f, ay0 = 0.f, ax1 = 0.f, ay1 = 0.f;
    float ax2 = 0.f, ay2 = 0.f, ax3 = 0.f, ay3 = 0.f;

    for (int base = b0; base < b4; base += AGG_BUF) {
        int cnt = min(AGG_BUF, b4 - base);
        for (int i = tid; i < cnt; i += 160) s_pk[i] = g_csr[base + i];
        __syncthreads();
        if (tid < 150) {
            const int hi = base + cnt;
            // Per-node sub-ranges inside this batch: no per-edge owner logic.
#define AGG_SEG(LOB, HIB, AX, AY)                                              \
            {                                                                  \
                int lo = max((LOB), base) - base;                              \
                int up = min((HIB), hi) - base;                                \
                _Pragma("unroll 4")                                            \
                for (int i = lo; i < up; i++) {                                \
                    int row = s_pk[i] & 0xFFFF;                                \
                    float2 f = __half22float2(                                 \
                        *(const __half2*)&g_hwh[row * DIM + 2 * tid]);         \
                    AX += f.x; AY += f.y;                                      \
                }                                                              \
            }
            AGG_SEG(b0, b1, ax0, ay0)
            AGG_SEG(b1, b2, ax1, ay1)
            AGG_SEG(b2, b3, ax2, ay2)
            AGG_SEG(b3, b4, ax3, ay3)
#undef AGG_SEG
        }
        __syncthreads();
    }

    if (tid < 150) {
        const float blv0 = bl[2 * tid], blv1 = bl[2 * tid + 1];
        float ssx = 0.f, ssy = 0.f, qqx = 0.f, qqy = 0.f;  // BN partials
#define AGG_WR(J, AX, AY)                                                      \
        {                                                                      \
            int n = n0 + (J);                                                  \
            float em = g_emsum[l * N_NODES + n] + selfE;                       \
            float2 s = __half22float2(                                         \
                *(const __half2*)&g_hwh[n * DIM + 2 * tid]);                   \
            float2 o;                                                          \
            o.x = (AX) + s.x + blv0 + em;                                      \
            o.y = (AY) + s.y + blv1 + em;                                      \
            *(float2*)&g_agg[n * DIM + 2 * tid] = o;                           \
            ssx += o.x; ssy += o.y;                                            \
            qqx += o.x * o.x; qqy += o.y * o.y;                                \
        }
        AGG_WR(0, ax0, ay0)
        AGG_WR(1, ax1, ay1)
        AGG_WR(2, ax2, ay2)
        AGG_WR(3, ax3, ay3)
#undef AGG_WR
        // fused BN statistics into one of NSC copies (contention / NSC)
        float* st = &g_stats[((size_t)l * NSC + (blockIdx.x & (NSC - 1))) *
                             2 * DIM];
        atomicAdd(&st[2 * tid], ssx);
        atomicAdd(&st[2 * tid + 1], ssy);
        atomicAdd(&st[DIM + 2 * tid], qqx);
        atomicAdd(&st[DIM + 2 * tid + 1], qqy);
    }
}

// ---------------- batch norm coefficients (folds NSC copies) ------------------
__global__ void coef_kernel(const float* __restrict__ gamma,
                            const float* __restrict__ beta, int l) {
    int d = blockIdx.x * blockDim.x + threadIdx.x;
    if (d >= DIM) return;
    const float* st = &g_stats[(size_t)l * NSC * 2 * DIM];
    float sum = 0.f, sq = 0.f;
#pragma unroll 8
    for (int c = 0; c < NSC; c++) {
        sum += st[c * 2 * DIM + d];
        sq += st[c * 2 * DIM + DIM + d];
    }
    const float inv_n = 1.0f / (float)N_NODES;
    float mu = sum * inv_n;
    float var = sq * inv_n - mu * mu;
    float s = rsqrtf(var + EPS) * gamma[l * DIM + d];
    g_coef[d] = s;
    g_coef[DIM + d] = beta[l * DIM + d] - mu * s;
}

// ---------------- pool (applies final BN; batch sorted -> segments) ----------
__global__ void gbound_kernel(const int* __restrict__ batch) {
    int g = blockIdx.x * blockDim.x + threadIdx.x;
    if (g > N_GRAPHS) return;
    int lo = 0, hi = N_NODES;
    while (lo < hi) {
        int mid = (lo + hi) >> 1;
        if (batch[mid] < g) lo = mid + 1; else hi = mid;
    }
    g_gstart[g] = lo;
}

__global__ __launch_bounds__(128)
void pool_kernel() {
    const int g = blockIdx.x;
    const int tid = threadIdx.x;
    const int gs = g_gstart[g], ge = g_gstart[g + 1];
    const int d0 = tid, d1 = tid + 128, d2 = tid + 256;
    float a0 = 0.f, a1 = 0.f, a2 = 0.f;
#pragma unroll 2
    for (int r = gs; r < ge; r++) {
        const float* p = g_agg + r * DIM;
        a0 += p[d0];
        a1 += p[d1];
        if (d2 < DIM) a2 += p[d2];
    }
    float inv = 1.0f / fmaxf((float)(ge - gs), 1.0f);
    float* op = g_hg + g * DIM;
    op[d0] = (a0 * inv) * g_coef[d0] + g_coef[DIM + d0];
    op[d1] = (a1 * inv) * g_coef[d1] + g_coef[DIM + d1];
    if (d2 < DIM) op[d2] = (a2 * inv) * g_coef[d2] + g_coef[DIM + d2];
}

// ---------------- head MLPs --------------------------------------------------
__global__ void gemm_feat(const float* __restrict__ fw,
                          const float* __restrict__ fb,
                          float* __restrict__ hfeat) {
    __shared__ float sh[DIM];
    int g = blockIdx.x;
    int t = threadIdx.x;  // 256
    for (int k = t; k < DIM; k += FEAT) sh[k] = g_hg[g * DIM + k];
    __syncthreads();
    float acc = fb[t];
    for (int k = 0; k < DIM; k++) acc += sh[k] * fw[k * FEAT + t];
    hfeat[g * FEAT + t] = acc;
}

__global__ void gemm_mlp1(const float* __restrict__ hfeat,
                          const float* __restrict__ w1,
                          const float* __restrict__ b1) {
    __shared__ float sh[FEAT];
    int g = blockIdx.x;
    int t = threadIdx.x;  // 256
    sh[t] = hfeat[g * FEAT + t];
    __syncthreads();
    float acc = b1[t];
    for (int k = 0; k < FEAT; k++) acc += sh[k] * w1[k * FEAT + t];
    g_hid[g * FEAT + t] = fmaxf(acc, 0.f);
}

__global__ void gemm_mlp2(const float* __restrict__ w2,
                          const float* __restrict__ b2,
                          float* __restrict__ out) {
    __shared__ float sh[FEAT];
    int g = blockIdx.x;
    int t = threadIdx.x;  // 128
    sh[t] = g_hid[g * FEAT + t];
    sh[t + 128] = g_hid[g * FEAT + t + 128];
    __syncthreads();
    float acc = b2[t];
    for (int k = 0; k < FEAT; k++) acc += sh[k] * w2[k * 128 + t];
    out[g * 128 + t] = acc;
}

// ---------------- launch -----------------------------------------------------
extern "C" void kernel_launch(void* const* d_in, const int* in_sizes, int n_in,
                              void* d_out, int out_size) {
    const int*   x     = (const int*)d_in[0];
    const int*   ei    = (const int*)d_in[1];
    const int*   ea    = (const int*)d_in[2];
    const int*   batch = (const int*)d_in[3];
    const float* emb1  = (const float*)d_in[4];
    const float* emb2  = (const float*)d_in[5];
    const float* W     = (const float*)d_in[6];
    const float* b     = (const float*)d_in[7];
    const float* e1    = (const float*)d_in[8];
    const float* e2    = (const float*)d_in[9];
    const float* gamma = (const float*)d_in[10];
    const float* beta  = (const float*)d_in[11];
    const float* fw    = (const float*)d_in[12];
    const float* fb    = (const float*)d_in[13];
    const float* w1    = (const float*)d_in[14];
    const float* b1    = (const float*)d_in[15];
    const float* w2    = (const float*)d_in[16];
    const float* b2    = (const float*)d_in[17];

    float* hfeat_out = (float*)d_out;
    float* final_out = (float*)d_out + N_GRAPHS * FEAT;

    __nv_bfloat16 *d_whi, *d_wlo;
    cudaGetSymbolAddress((void**)&d_whi, g_whi);
    cudaGetSymbolAddress((void**)&d_wlo, g_wlo);

    cudaFuncSetAttribute(gemm_layer_tc,
                         cudaFuncAttributeMaxDynamicSharedMemorySize,
                         (int)GEMM_SMEM);

    dim3 ggrid((DIM + 63) / 64, (N_NODES + 127) / 128);  // 5 x 391
    const int plane_blocks = (AROWS * ACOLS + 255) / 256;
    const int conv_blocks = (N_NODES * 75 + 255) / 256;

    // Launch order keeps gemm_layer_tc(l=0) at position #4 for ncu attribution.
    wconv_kernel<<<(N_LAYERS * WROWS * WCOLS + 255) / 256, 256>>>(W);   // 1
    embed_kernel<<<plane_blocks, 256>>>(x, emb1, emb2);                 // 2
    hist_kernel<<<(N_EDGES + 255) / 256, 256>>>(ei);                    // 3
    gemm_layer_tc<<<ggrid, 256, GEMM_SMEM>>>(d_whi, d_wlo);             // 4 (l=0)
    scan1_kernel<<<NBLK_SCAN, 256>>>();                                 // 5
    scan2_kernel<<<1, 256>>>();                                         // 6
    scan3_kernel<<<(N_NODES + 255) / 256, 256>>>();                     // 7
    fill_kernel<<<(N_EDGES + 255) / 256, 256>>>(ei, ea);                // 8
    emsum_kernel<<<NBLK_SCAN, 256>>>(e1, e2);                           // 9

    for (int l = 0; l < N_LAYERS; l++) {
        if (l > 0)
            gemm_layer_tc<<<ggrid, 256, GEMM_SMEM>>>(
                d_whi + (size_t)l * WROWS * WCOLS,
                d_wlo + (size_t)l * WROWS * WCOLS);
        agg_kernel<<<N_NODES / AGG_NODES, 160>>>(b + l * DIM, e1, e2, l);
        coef_kernel<<<2, 256>>>(gamma, beta, l);
        if (l < N_LAYERS - 1)
            convert_kernel<<<conv_blocks, 256>>>();
    }

    gbound_kernel<<<(N_GRAPHS + 256) / 256, 256>>>(batch);
    pool_kernel<<<N_GRAPHS, 128>>>();

    gemm_feat<<<N_GRAPHS, FEAT>>>(fw, fb, hfeat_out);
    gemm_mlp1<<<N_GRAPHS, FEAT>>>(hfeat_out, w1, b1);
    gemm_mlp2<<<N_GRAPHS, 128>>>(w2, b2, final_out);
}

// round 17
// speedup vs baseline: 1.9313x; 1.4920x over previous
#include <cuda_runtime.h>
#include <cuda_fp16.h>
#include <cuda_bf16.h>
#include <cstdint>

#define N_NODES 50000
#define N_EDGES 800000
#define N_GRAPHS 1024
#define DIM 300
#define N_LAYERS 5
#define FEAT 256
#define EPS 1e-5f
#define NBLK_SCAN ((N_NODES + 255) / 256)   // 196
#define NSC 32   // stat copies (contention spreading)

// padded plane geometry (no predicates in GEMM staging)
#define AROWS 50048        // 391 * 128
#define ACOLS 304          // 19 * 16
#define WROWS 304
#define WCOLS 320

// ---------------- scratch (static device globals; no allocation) -------------
__device__ __align__(16) __nv_bfloat16 g_ahi[AROWS * ACOLS];  // 30.4 MB
__device__ __align__(16) __nv_bfloat16 g_alo[AROWS * ACOLS];
__device__ __align__(16) __nv_bfloat16 g_whi[N_LAYERS * WROWS * WCOLS];
__device__ __align__(16) __nv_bfloat16 g_wlo[N_LAYERS * WROWS * WCOLS];
__device__ __half g_hwh[N_NODES * DIM];   // h @ W[l] in fp16 (30 MB)
__device__ float  g_agg[N_NODES * DIM];   // pre-BN accumulation
__device__ float  g_stats[N_LAYERS * NSC * 2 * DIM];  // 32 copies per layer
__device__ float  g_coef[2 * DIM];        // current layer BN scale/shift
__device__ float  g_emsum[N_LAYERS * N_NODES];  // per-node edge-emb sums
__device__ float  g_hg[N_GRAPHS * DIM];
__device__ float  g_hid[N_GRAPHS * FEAT];
// CSR build
__device__ int g_deg[N_NODES];
__device__ int g_incl[N_NODES];
__device__ int g_bsum[NBLK_SCAN];
__device__ int g_boff[NBLK_SCAN];
__device__ int g_cursor[N_NODES];
__device__ int g_start[N_NODES + 1];
__device__ int g_csr[N_EDGES];           // row | (attr<<16)
__device__ int g_gstart[N_GRAPHS + 1];

// ---------------- weight split: W -> bf16 hi/lo padded planes ----------------
__global__ void wconv_kernel(const float* __restrict__ W) {
    int i = blockIdx.x * blockDim.x + threadIdx.x;
    if (i >= N_LAYERS * WROWS * WCOLS) return;
    int l = i / (WROWS * WCOLS);
    int r = i - l * (WROWS * WCOLS);
    int k = r / WCOLS, n = r - k * WCOLS;
    float v = (k < DIM && n < DIM) ? W[(size_t)l * DIM * DIM + k * DIM + n] : 0.f;
    __nv_bfloat16 h = __float2bfloat16_rn(v);
    g_whi[i] = h;
    g_wlo[i] = __float2bfloat16_rn(v - __bfloat162float(h));
}

// ---------------- node embedding -> layer-0 A planes; zero deg/stats ---------
__global__ void embed_kernel(const int* __restrict__ x,
                             const float* __restrict__ emb1,
                             const float* __restrict__ emb2) {
    int i = blockIdx.x * blockDim.x + threadIdx.x;
    if (i < N_LAYERS * NSC * 2 * DIM) g_stats[i] = 0.f;
    if (i < N_NODES) g_deg[i] = 0;
    if (i >= AROWS * ACOLS) return;
    int n = i / ACOLS, d = i - n * ACOLS;
    float v = 0.f;
    if (n < N_NODES && d < DIM)
        v = emb1[x[2 * n] * DIM + d] + emb2[x[2 * n + 1] * DIM + d];
    __nv_bfloat16 h = __float2bfloat16_rn(v);
    g_ahi[i] = h;
    g_alo[i] = __float2bfloat16_rn(v - __bfloat162float(h));
}

// ---------------- per-layer BN+ReLU convert: g_agg -> A planes (float4) ------
// 300 = 75*4 exactly; pad rows/cols stay zero from embed (never rewritten).
__global__ void convert_kernel() {
    int i = blockIdx.x * blockDim.x + threadIdx.x;  // chunk id
    if (i >= N_NODES * 75) return;
    int n = i / 75, c = i - n * 75;
    int d = 4 * c;
    const float4 v = *(const float4*)&g_agg[n * DIM + d];
    const float4 s = *(const float4*)&g_coef[d];
    const float4 t = *(const float4*)&g_coef[DIM + d];
    float f0 = fmaxf(v.x * s.x + t.x, 0.f);
    float f1 = fmaxf(v.y * s.y + t.y, 0.f);
    float f2 = fmaxf(v.z * s.z + t.z, 0.f);
    float f3 = fmaxf(v.w * s.w + t.w, 0.f);
    __nv_bfloat16 h0 = __float2bfloat16_rn(f0);
    __nv_bfloat16 h1 = __float2bfloat16_rn(f1);
    __nv_bfloat16 h2 = __float2bfloat16_rn(f2);
    __nv_bfloat16 h3 = __float2bfloat16_rn(f3);
    unsigned hu0 = (unsigned)__bfloat16_as_ushort(h0) |
                   ((unsigned)__bfloat16_as_ushort(h1) << 16);
    unsigned hu1 = (unsigned)__bfloat16_as_ushort(h2) |
                   ((unsigned)__bfloat16_as_ushort(h3) << 16);
    __nv_bfloat16 l0 = __float2bfloat16_rn(f0 - __bfloat162float(h0));
    __nv_bfloat16 l1 = __float2bfloat16_rn(f1 - __bfloat162float(h1));
    __nv_bfloat16 l2 = __float2bfloat16_rn(f2 - __bfloat162float(h2));
    __nv_bfloat16 l3 = __float2bfloat16_rn(f3 - __bfloat162float(h3));
    unsigned lu0 = (unsigned)__bfloat16_as_ushort(l0) |
                   ((unsigned)__bfloat16_as_ushort(l1) << 16);
    unsigned lu1 = (unsigned)__bfloat16_as_ushort(l2) |
                   ((unsigned)__bfloat16_as_ushort(l3) << 16);
    size_t off = (size_t)n * ACOLS + d;
    *(uint2*)&g_ahi[off] = make_uint2(hu0, hu1);
    *(uint2*)&g_alo[off] = make_uint2(lu0, lu1);
}

// ---------------- CSR build ---------------------------------------------------
__global__ void hist_kernel(const int* __restrict__ ei) {
    int e = blockIdx.x * blockDim.x + threadIdx.x;
    if (e >= N_EDGES) return;
    atomicAdd(&g_deg[ei[N_EDGES + e]], 1);
}

__global__ void scan1_kernel() {
    __shared__ int s[256];
    int tid = threadIdx.x;
    int i = blockIdx.x * 256 + tid;
    int v = (i < N_NODES) ? g_deg[i] : 0;
    s[tid] = v;
    __syncthreads();
#pragma unroll
    for (int off = 1; off < 256; off <<= 1) {
        int t = (tid >= off) ? s[tid - off] : 0;
        __syncthreads();
        s[tid] += t;
        __syncthreads();
    }
    if (i < N_NODES) g_incl[i] = s[tid];
    if (tid == 255) g_bsum[blockIdx.x] = s[255];
}

__global__ void scan2_kernel() {
    __shared__ int s[256];
    int tid = threadIdx.x;
    s[tid] = (tid < NBLK_SCAN) ? g_bsum[tid] : 0;
    __syncthreads();
#pragma unroll
    for (int off = 1; off < 256; off <<= 1) {
        int t = (tid >= off) ? s[tid - off] : 0;
        __syncthreads();
        s[tid] += t;
        __syncthreads();
    }
    if (tid < NBLK_SCAN) g_boff[tid] = s[tid] - g_bsum[tid];
}

__global__ void scan3_kernel() {
    int i = blockIdx.x * blockDim.x + threadIdx.x;
    if (i >= N_NODES) return;
    g_start[i + 1] = g_incl[i] + g_boff[i >> 8];
    g_cursor[i] = 0;
    if (i == 0) g_start[0] = 0;
}

__global__ void fill_kernel(const int* __restrict__ ei,
                            const int* __restrict__ ea) {
    int e = blockIdx.x * blockDim.x + threadIdx.x;
    if (e >= N_EDGES) return;
    int row = ei[e];
    int col = ei[N_EDGES + e];
    int attr = ea[2 * e] * 3 + ea[2 * e + 1];  // 0..8
    int pos = g_start[col] + atomicAdd(&g_cursor[col], 1);
    g_csr[pos] = row | (attr << 16);
}

// per-node sum of scalar edge embeddings, all layers at once
__global__ void emsum_kernel(const float* __restrict__ e1,
                             const float* __restrict__ e2) {
    __shared__ float tab[N_LAYERS][9];
    int tid = threadIdx.x;
    if (tid < N_LAYERS * 9) {
        int l = tid / 9, a = tid % 9;
        tab[l][a] = e1[l * 5 + a / 3] + e2[l * 3 + a % 3];
    }
    __syncthreads();
    int n = blockIdx.x * blockDim.x + tid;
    if (n >= N_NODES) return;
    float s[N_LAYERS] = {0.f, 0.f, 0.f, 0.f, 0.f};
    int e0 = g_start[n], e1i = g_start[n + 1];
    for (int e = e0; e < e1i; e++) {
        int a = g_csr[e] >> 16;
#pragma unroll
        for (int l = 0; l < N_LAYERS; l++) s[l] += tab[l][a];
    }
#pragma unroll
    for (int l = 0; l < N_LAYERS; l++) g_emsum[l * N_NODES + n] = s[l];
}

// ---------------- 3xBF16 tensor-core GEMM (3-stage cp.async + ldmatrix) ------
#define MMA_BF16(cc, A0, A1, A2, A3, B0, B1)                                   \
    asm volatile(                                                              \
        "mma.sync.aligned.m16n8k16.row.col.f32.bf16.bf16.f32 "                 \
        "{%0,%1,%2,%3},{%4,%5,%6,%7},{%8,%9},{%0,%1,%2,%3};"                   \
        : "+f"(cc[0]), "+f"(cc[1]), "+f"(cc[2]), "+f"(cc[3])                   \
        : "r"(A0), "r"(A1), "r"(A2), "r"(A3), "r"(B0), "r"(B1));

__device__ __forceinline__ void ldsm_x4(unsigned& r0, unsigned& r1,
                                        unsigned& r2, unsigned& r3,
                                        unsigned addr) {
    asm volatile("ldmatrix.sync.aligned.m8n8.x4.shared.b16 {%0,%1,%2,%3}, [%4];"
                 : "=r"(r0), "=r"(r1), "=r"(r2), "=r"(r3) : "r"(addr));
}
__device__ __forceinline__ void ldsm_x4_t(unsigned& r0, unsigned& r1,
                                          unsigned& r2, unsigned& r3,
                                          unsigned addr) {
    asm volatile(
        "ldmatrix.sync.aligned.m8n8.x4.trans.shared.b16 {%0,%1,%2,%3}, [%4];"
        : "=r"(r0), "=r"(r1), "=r"(r2), "=r"(r3) : "r"(addr));
}
__device__ __forceinline__ void cp16(void* dst_smem, const void* src) {
    unsigned d = (unsigned)__cvta_generic_to_shared(dst_smem);
    asm volatile("cp.async.cg.shared.global [%0], [%1], 16;"
                 :: "r"(d), "l"(src) : "memory");
}

#define NKT 19   // ceil(300/16)
#define A_RS 24  // A row stride in bf16 (48 B -> group 3m mod 8, conflict-free)
#define B_RS 72  // B row stride in bf16 (144 B -> group k mod 8, conflict-free)
#define GSTAGES 3
#define A_PLANE (128 * A_RS)   // bf16 per stage per plane
#define B_PLANE (16 * B_RS)
#define GEMM_SMEM ((size_t)GSTAGES * (2 * A_PLANE + 2 * B_PLANE) * 2)  // 50688 B

__global__ __launch_bounds__(256)
void gemm_layer_tc(const __nv_bfloat16* __restrict__ Whi,
                   const __nv_bfloat16* __restrict__ Wlo) {
    extern __shared__ __align__(16) __nv_bfloat16 smp[];
    __nv_bfloat16* Ahi = smp;                          // [GSTAGES][128][A_RS]
    __nv_bfloat16* Alo = Ahi + GSTAGES * A_PLANE;
    __nv_bfloat16* Bhi = Alo + GSTAGES * A_PLANE;      // [GSTAGES][16][B_RS]
    __nv_bfloat16* Blo = Bhi + GSTAGES * B_PLANE;

    const int tid = threadIdx.x;
    const int lane = tid & 31;
    const int warp = tid >> 5;
    const int g = lane >> 2;      // 0..7
    const int tg = lane & 3;      // 0..3
    const int wm = warp >> 1;     // 0..3 (m)
    const int wn = warp & 1;      // 0..1 (n)
    const int m0 = blockIdx.y * 128;
    const int n0 = blockIdx.x * 64;

    float c[2][4][4];
#pragma unroll
    for (int im = 0; im < 2; im++)
#pragma unroll
        for (int in = 0; in < 4; in++)
#pragma unroll
            for (int j = 0; j < 4; j++) c[im][in][j] = 0.f;

    // A staging: row a_m = tid&127, k-half (8 bf16 = 16 B) = tid>>7
    const int a_m = tid & 127;
    const int a_kh = tid >> 7;
    const size_t a_goff = (size_t)(m0 + a_m) * ACOLS + a_kh * 8;
    // B staging: 128 chunks of 16 B per plane; tid<128 -> hi plane, else lo
    const int b_idx = tid & 127;
    const int b_k = b_idx >> 3;            // 0..15
    const int b_nc = (b_idx & 7) * 8;      // 0..56
    const bool b_is_hi = (tid < 128);
    const __nv_bfloat16* wsrc = b_is_hi ? Whi : Wlo;

    auto stage = [&](int kt) {
        int buf = kt % GSTAGES;
        cp16(Ahi + (buf * 128 + a_m) * A_RS + a_kh * 8,
             g_ahi + a_goff + kt * 16);
        cp16(Alo + (buf * 128 + a_m) * A_RS + a_kh * 8,
             g_alo + a_goff + kt * 16);
        __nv_bfloat16* bd = (b_is_hi ? Bhi : Blo) + (buf * 16 + b_k) * B_RS + b_nc;
        cp16(bd, wsrc + (size_t)(kt * 16 + b_k) * WCOLS + n0 + b_nc);
        asm volatile("cp.async.commit_group;" ::: "memory");
    };

    // ldmatrix per-thread source offsets
    const int a_row = (lane & 15);
    const int a_chk = (lane >> 4) * 8;
    const int b_row = ((lane >> 3) & 1) * 8 + (lane & 7);
    const int b_chk = (lane >> 4) * 8;

    stage(0);
    stage(1);

#pragma unroll 1
    for (int kt = 0; kt < NKT; kt++) {
        const int buf = kt % GSTAGES;
        if (kt < NKT - 1)
            asm volatile("cp.async.wait_group 1;" ::: "memory");
        else
            asm volatile("cp.async.wait_group 0;" ::: "memory");
        __syncthreads();

        {
            unsigned ah[2][4], al[2][4];
#pragma unroll
            for (int im = 0; im < 2; im++) {
                int mrow = buf * 128 + wm * 32 + im * 16 + a_row;
                unsigned ahh = (unsigned)__cvta_generic_to_shared(
                    Ahi + mrow * A_RS + a_chk);
                unsigned all_ = (unsigned)__cvta_generic_to_shared(
                    Alo + mrow * A_RS + a_chk);
                ldsm_x4(ah[im][0], ah[im][1], ah[im][2], ah[im][3], ahh);
                ldsm_x4(al[im][0], al[im][1], al[im][2], al[im][3], all_);
            }
            unsigned bh[4][2], bl[4][2];
#pragma unroll
            for (int pair = 0; pair < 2; pair++) {
                int ncol = wn * 32 + pair * 16 + b_chk;
                int brw = buf * 16 + b_row;
                unsigned bhh = (unsigned)__cvta_generic_to_shared(
                    Bhi + brw * B_RS + ncol);
                unsigned bll = (unsigned)__cvta_generic_to_shared(
                    Blo + brw * B_RS + ncol);
                ldsm_x4_t(bh[2 * pair][0], bh[2 * pair][1],
                          bh[2 * pair + 1][0], bh[2 * pair + 1][1], bhh);
                ldsm_x4_t(bl[2 * pair][0], bl[2 * pair][1],
                          bl[2 * pair + 1][0], bl[2 * pair + 1][1], bll);
            }
#pragma unroll
            for (int im = 0; im < 2; im++)
#pragma unroll
                for (int in = 0; in < 4; in++) {
                    MMA_BF16(c[im][in], al[im][0], al[im][1], al[im][2],
                             al[im][3], bh[in][0], bh[in][1]);
                    MMA_BF16(c[im][in], ah[im][0], ah[im][1], ah[im][2],
                             ah[im][3], bl[in][0], bl[in][1]);
                    MMA_BF16(c[im][in], ah[im][0], ah[im][1], ah[im][2],
                             ah[im][3], bh[in][0], bh[in][1]);
                }
        }

        // Stage kt+2 into buffer (kt+2)%3 = (kt-1)%3. All threads finished
        // reading that buffer (compute kt-1) before this iteration's barrier.
        if (kt + 2 < NKT) stage(kt + 2);
    }

    // ---- epilogue: write g_hwh (fp16, half2 stores) ----
#pragma unroll
    for (int in = 0; in < 4; in++) {
        int ncol = n0 + wn * 32 + in * 8 + 2 * tg;
        if (ncol >= DIM) continue;
#pragma unroll
        for (int im = 0; im < 2; im++) {
            int r0 = m0 + wm * 32 + im * 16 + g;
            if (r0 < N_NODES)
                *(__half2*)&g_hwh[r0 * DIM + ncol] =
                    __floats2half2_rn(c[im][in][0], c[im][in][1]);
            int r1 = r0 + 8;
            if (r1 < N_NODES)
                *(__half2*)&g_hwh[r1 * DIM + ncol] =
                    __floats2half2_rn(c[im][in][2], c[im][in][3]);
        }
    }
}

// -- CSR aggregation: 4 nodes/block, segmented sub-loops, 32-copy fused stats --
#define AGG_NODES 4
#define AGG_BUF 640

__global__ __launch_bounds__(160)
void agg_kernel(const float* __restrict__ bl,
                const float* __restrict__ e1,
                const float* __restrict__ e2,
                int l) {
    __shared__ int s_pk[AGG_BUF];
    const int n0 = blockIdx.x * AGG_NODES;
    const int tid = threadIdx.x;
    const int b0 = g_start[n0];
    const int b1 = g_start[n0 + 1];
    const int b2 = g_start[n0 + 2];
    const int b3 = g_start[n0 + 3];
    const int b4 = g_start[n0 + 4];
    const float selfE = e1[l * 5 + 4] + e2[l * 3 + 0];

    float ax0 = 0.f, ay0 = 0.f, ax1 = 0.f, ay1 = 0.f;
    float ax2 = 0.f, ay2 = 0.f, ax3 = 0.f, ay3 = 0.f;

    for (int base = b0; base < b4; base += AGG_BUF) {
        int cnt = min(AGG_BUF, b4 - base);
        for (int i = tid; i < cnt; i += 160) s_pk[i] = g_csr[base + i];
        __syncthreads();
        if (tid < 150) {
            const int hi = base + cnt;
            // Per-node sub-ranges inside this batch: no per-edge owner logic.
#define AGG_SEG(LOB, HIB, AX, AY)                                              \
            {                                                                  \
                int lo = max((LOB), base) - base;                              \
                int up = min((HIB), hi) - base;                                \
                _Pragma("unroll 4")                                            \
                for (int i = lo; i < up; i++) {                                \
                    int row = s_pk[i] & 0xFFFF;                                \
                    float2 f = __half22float2(                                 \
                        *(const __half2*)&g_hwh[row * DIM + 2 * tid]);         \
                    AX += f.x; AY += f.y;                                      \
                }                                                              \
            }
            AGG_SEG(b0, b1, ax0, ay0)
            AGG_SEG(b1, b2, ax1, ay1)
            AGG_SEG(b2, b3, ax2, ay2)
            AGG_SEG(b3, b4, ax3, ay3)
#undef AGG_SEG
        }
        __syncthreads();
    }

    if (tid < 150) {
        const float blv0 = bl[2 * tid], blv1 = bl[2 * tid + 1];
        float ssx = 0.f, ssy = 0.f, qqx = 0.f, qqy = 0.f;  // BN partials
#define AGG_WR(J, AX, AY)                                                      \
        {                                                                      \
            int n = n0 + (J);                                                  \
            float em = g_emsum[l * N_NODES + n] + selfE;                       \
            float2 s = __half22float2(                                         \
                *(const __half2*)&g_hwh[n * DIM + 2 * tid]);                   \
            float2 o;                                                          \
            o.x = (AX) + s.x + blv0 + em;                                      \
            o.y = (AY) + s.y + blv1 + em;                                      \
            *(float2*)&g_agg[n * DIM + 2 * tid] = o;                           \
            ssx += o.x; ssy += o.y;                                            \
            qqx += o.x * o.x; qqy += o.y * o.y;                                \
        }
        AGG_WR(0, ax0, ay0)
        AGG_WR(1, ax1, ay1)
        AGG_WR(2, ax2, ay2)
        AGG_WR(3, ax3, ay3)
#undef AGG_WR
        // fused BN statistics into one of NSC copies (contention / NSC)
        float* st = &g_stats[((size_t)l * NSC + (blockIdx.x & (NSC - 1))) *
                             2 * DIM];
        atomicAdd(&st[2 * tid], ssx);
        atomicAdd(&st[2 * tid + 1], ssy);
        atomicAdd(&st[DIM + 2 * tid], qqx);
        atomicAdd(&st[DIM + 2 * tid + 1], qqy);
    }
}

// ---------------- batch norm coefficients (folds NSC copies) ------------------
__global__ void coef_kernel(const float* __restrict__ gamma,
                            const float* __restrict__ beta, int l) {
    int d = blockIdx.x * blockDim.x + threadIdx.x;
    if (d >= DIM) return;
    const float* st = &g_stats[(size_t)l * NSC * 2 * DIM];
    float sum = 0.f, sq = 0.f;
#pragma unroll 8
    for (int c = 0; c < NSC; c++) {
        sum += st[c * 2 * DIM + d];
        sq += st[c * 2 * DIM + DIM + d];
    }
    const float inv_n = 1.0f / (float)N_NODES;
    float mu = sum * inv_n;
    float var = sq * inv_n - mu * mu;
    float s = rsqrtf(var + EPS) * gamma[l * DIM + d];
    g_coef[d] = s;
    g_coef[DIM + d] = beta[l * DIM + d] - mu * s;
}

// ---------------- pool (applies final BN; batch sorted -> segments) ----------
__global__ void gbound_kernel(const int* __restrict__ batch) {
    int g = blockIdx.x * blockDim.x + threadIdx.x;
    if (g > N_GRAPHS) return;
    int lo = 0, hi = N_NODES;
    while (lo < hi) {
        int mid = (lo + hi) >> 1;
        if (batch[mid] < g) lo = mid + 1; else hi = mid;
    }
    g_gstart[g] = lo;
}

__global__ __launch_bounds__(128)
void pool_kernel() {
    const int g = blockIdx.x;
    const int tid = threadIdx.x;
    const int gs = g_gstart[g], ge = g_gstart[g + 1];
    const int d0 = tid, d1 = tid + 128, d2 = tid + 256;
    float a0 = 0.f, a1 = 0.f, a2 = 0.f;
#pragma unroll 2
    for (int r = gs; r < ge; r++) {
        const float* p = g_agg + r * DIM;
        a0 += p[d0];
        a1 += p[d1];
        if (d2 < DIM) a2 += p[d2];
    }
    float inv = 1.0f / fmaxf((float)(ge - gs), 1.0f);
    float* op = g_hg + g * DIM;
    op[d0] = (a0 * inv) * g_coef[d0] + g_coef[DIM + d0];
    op[d1] = (a1 * inv) * g_coef[d1] + g_coef[DIM + d1];
    if (d2 < DIM) op[d2] = (a2 * inv) * g_coef[d2] + g_coef[DIM + d2];
}

// ---------------- head MLPs --------------------------------------------------
__global__ void gemm_feat(const float* __restrict__ fw,
                          const float* __restrict__ fb,
                          float* __restrict__ hfeat) {
    __shared__ float sh[DIM];
    int g = blockIdx.x;
    int t = threadIdx.x;  // 256
    for (int k = t; k < DIM; k += FEAT) sh[k] = g_hg[g * DIM + k];
    __syncthreads();
    float acc = fb[t];
    for (int k = 0; k < DIM; k++) acc += sh[k] * fw[k * FEAT + t];
    hfeat[g * FEAT + t] = acc;
}

__global__ void gemm_mlp1(const float* __restrict__ hfeat,
                          const float* __restrict__ w1,
                          const float* __restrict__ b1) {
    __shared__ float sh[FEAT];
    int g = blockIdx.x;
    int t = threadIdx.x;  // 256
    sh[t] = hfeat[g * FEAT + t];
    __syncthreads();
    float acc = b1[t];
    for (int k = 0; k < FEAT; k++) acc += sh[k] * w1[k * FEAT + t];
    g_hid[g * FEAT + t] = fmaxf(acc, 0.f);
}

__global__ void gemm_mlp2(const float* __restrict__ w2,
                          const float* __restrict__ b2,
                          float* __restrict__ out) {
    __shared__ float sh[FEAT];
    int g = blockIdx.x;
    int t = threadIdx.x;  // 128
    sh[t] = g_hid[g * FEAT + t];
    sh[t + 128] = g_hid[g * FEAT + t + 128];
    __syncthreads();
    float acc = b2[t];
    for (int k = 0; k < FEAT; k++) acc += sh[k] * w2[k * 128 + t];
    out[g * 128 + t] = acc;
}

// ---------------- launch -----------------------------------------------------
extern "C" void kernel_launch(void* const* d_in, const int* in_sizes, int n_in,
                              void* d_out, int out_size) {
    const int*   x     = (const int*)d_in[0];
    const int*   ei    = (const int*)d_in[1];
    const int*   ea    = (const int*)d_in[2];
    const int*   batch = (const int*)d_in[3];
    const float* emb1  = (const float*)d_in[4];
    const float* emb2  = (const float*)d_in[5];
    const float* W     = (const float*)d_in[6];
    const float* b     = (const float*)d_in[7];
    const float* e1    = (const float*)d_in[8];
    const float* e2    = (const float*)d_in[9];
    const float* gamma = (const float*)d_in[10];
    const float* beta  = (const float*)d_in[11];
    const float* fw    = (const float*)d_in[12];
    const float* fb    = (const float*)d_in[13];
    const float* w1    = (const float*)d_in[14];
    const float* b1    = (const float*)d_in[15];
    const float* w2    = (const float*)d_in[16];
    const float* b2    = (const float*)d_in[17];

    float* hfeat_out = (float*)d_out;
    float* final_out = (float*)d_out + N_GRAPHS * FEAT;

    __nv_bfloat16 *d_whi, *d_wlo;
    cudaGetSymbolAddress((void**)&d_whi, g_whi);
    cudaGetSymbolAddress((void**)&d_wlo, g_wlo);

    cudaFuncSetAttribute(gemm_layer_tc,
                         cudaFuncAttributeMaxDynamicSharedMemorySize,
                         (int)GEMM_SMEM);

    dim3 ggrid((DIM + 63) / 64, (N_NODES + 127) / 128);  // 5 x 391
    const int plane_blocks = (AROWS * ACOLS + 255) / 256;
    const int conv_blocks = (N_NODES * 75 + 255) / 256;

    // Launch order keeps gemm_layer_tc(l=0) at position #4 for ncu attribution.
    wconv_kernel<<<(N_LAYERS * WROWS * WCOLS + 255) / 256, 256>>>(W);   // 1
    embed_kernel<<<plane_blocks, 256>>>(x, emb1, emb2);                 // 2
    hist_kernel<<<(N_EDGES + 255) / 256, 256>>>(ei);                    // 3
    gemm_layer_tc<<<ggrid, 256, GEMM_SMEM>>>(d_whi, d_wlo);             // 4 (l=0)
    scan1_kernel<<<NBLK_SCAN, 256>>>();                                 // 5
    scan2_kernel<<<1, 256>>>();                                         // 6
    scan3_kernel<<<(N_NODES + 255) / 256, 256>>>();                     // 7
    fill_kernel<<<(N_EDGES + 255) / 256, 256>>>(ei, ea);                // 8
    emsum_kernel<<<NBLK_SCAN, 256>>>(e1, e2);                           // 9

    for (int l = 0; l < N_LAYERS; l++) {
        if (l > 0)
            gemm_layer_tc<<<ggrid, 256, GEMM_SMEM>>>(
                d_whi + (size_t)l * WROWS * WCOLS,
                d_wlo + (size_t)l * WROWS * WCOLS);
        agg_kernel<<<N_NODES / AGG_NODES, 160>>>(b + l * DIM, e1, e2, l);
        coef_kernel<<<2, 256>>>(gamma, beta, l);
        if (l < N_LAYERS - 1)
            convert_kernel<<<conv_blocks, 256>>>();
    }

    gbound_kernel<<<(N_GRAPHS + 256) / 256, 256>>>(batch);
    pool_kernel<<<N_GRAPHS, 128>>>();

    gemm_feat<<<N_GRAPHS, FEAT>>>(fw, fb, hfeat_out);
    gemm_mlp1<<<N_GRAPHS, FEAT>>>(hfeat_out, w1, b1);
    gemm_mlp2<<<N_GRAPHS, 128>>>(w2, b2, final_out);
}